// round 10
// baseline (speedup 1.0000x reference)
#include <cuda_runtime.h>

#define EPS_F 1e-16f
#define NEG_SLOPE 0.2f

static const int MAXN = 50048;
static const int MAXE = 850048;
static const int NBMAX = 64;

// scratch (device globals — no allocation allowed)
__device__ int   g_deg[MAXN];
__device__ int   g_off[MAXN + 1];
__device__ int   g_cur[MAXN];
__device__ int   g_csr_src[MAXE];
__device__ int   g_csr_eid[MAXE];
__device__ float g_ew[MAXE];
__device__ int   g_bsum[NBMAX];
__device__ int   g_scanDone;
__device__ __align__(16) float g_h1[(size_t)MAXN * 64];
__device__ __align__(16) float g_h2[(size_t)MAXN * 64];
__device__ __align__(16) float g_h3[(size_t)MAXN * 32];
__device__ __align__(16) float g_aggA[(size_t)MAXN * 64];
__device__ __align__(16) float g_aggB[(size_t)MAXN * 64];
__device__ float g_asA[MAXN];
__device__ float g_adA[MAXN];
__device__ float g_asB[MAXN];
__device__ float g_adB[MAXN];
__device__ float g_asC[MAXN];
__device__ float g_adC[MAXN];
__device__ int   g_is64;

// ---------------------------------------------------------------------------
// init: tiny 1-block kernel — dtype detect + scan counter reset.
// (g_deg is zeroed by scan_single after it consumes it, so no O(N) pass.)
// ---------------------------------------------------------------------------
__global__ void init_kernel(const int* __restrict__ ei32) {
    if (threadIdx.x == 0) {
        g_scanDone = 0;
        int all_zero = 1;
        #pragma unroll
        for (int k = 0; k < 64; k++)
            if (ei32[2 * k + 1] != 0) { all_zero = 0; break; }
        g_is64 = all_zero;
    }
}

// ---------------------------------------------------------------------------
__device__ __forceinline__ void load_edge(const int* __restrict__ ei32,
                                          int e, int E, int n, int& s, int& d) {
    if (e < E) {
        if (g_is64) {
            const long long* ei = (const long long*)ei32;
            s = (int)ei[e]; d = (int)ei[E + e];
        } else {
            s = ei32[e]; d = ei32[E + e];
        }
    } else {
        s = d = e - E;   // self loop
    }
    s = min(max(s, 0), n - 1);
    d = min(max(d, 0), n - 1);
}

// Count per-dst degree; emit stacked (src,dst) as float at head of d_out.
__global__ void build_edges(const int* __restrict__ ei32, int E, int Ep, int n,
                            float* __restrict__ outIdx) {
    int e = blockIdx.x * blockDim.x + threadIdx.x;
    if (e >= Ep) return;
    int s, d;
    load_edge(ei32, e, E, n, s, d);
    atomicAdd(&g_deg[d], 1);
    outIdx[e]      = (float)s;
    outIdx[Ep + e] = (float)d;
}

// ---------------------------------------------------------------------------
// Single-pass scan (49 blocks, all resident): block scans its 1024-chunk,
// publishes total, spins until all published, adds prefix of preceding
// totals. Also re-zeroes g_deg after consuming it (for the next replay).
// ---------------------------------------------------------------------------
__global__ void scan_single(int n, int nb) {
    __shared__ int warpsum[32];
    __shared__ int s_base;
    int tid = threadIdx.x, lane = tid & 31, wid = tid >> 5;
    int i = blockIdx.x * 1024 + tid;
    int v = (i < n) ? g_deg[i] : 0;
    if (i < n) g_deg[i] = 0;                    // consume-and-reset

    int incl = v;
    #pragma unroll
    for (int off = 1; off < 32; off <<= 1) {
        int t = __shfl_up_sync(0xffffffffu, incl, off);
        if (lane >= off) incl += t;
    }
    if (lane == 31) warpsum[wid] = incl;
    __syncthreads();
    if (wid == 0) {
        int ws = warpsum[lane];
        int wincl = ws;
        #pragma unroll
        for (int off = 1; off < 32; off <<= 1) {
            int t = __shfl_up_sync(0xffffffffu, wincl, off);
            if (lane >= off) wincl += t;
        }
        warpsum[lane] = wincl - ws;
    }
    __syncthreads();
    incl += warpsum[wid];                       // block-inclusive

    if (tid == 1023) {
        g_bsum[blockIdx.x] = incl;
        __threadfence();
        atomicAdd(&g_scanDone, 1);
    }
    if (tid == 0) {
        while (atomicAdd(&g_scanDone, 0) < nb) { }
        int b = 0;
        for (int j = 0; j < blockIdx.x; j++)
            b += *(volatile int*)&g_bsum[j];
        s_base = b;
    }
    __syncthreads();

    int excl = incl - v + s_base;
    if (i < n) {
        g_off[i] = excl;
        g_cur[i] = excl;
        if (i == n - 1) g_off[n] = excl + v;
    }
}

__global__ void place_edges(const int* __restrict__ ei32, int E, int Ep, int n) {
    int e = blockIdx.x * blockDim.x + threadIdx.x;
    if (e >= Ep) return;
    int s, d;
    load_edge(ei32, e, E, n, s, d);
    int pos = atomicAdd(&g_cur[d], 1);
    g_csr_src[pos] = s;
    g_csr_eid[pos] = e;
}

// ---------------------------------------------------------------------------
// GEMM over row range [rlo, rhi): h = in @ W^T ; as/ad dot-products.
// 4 warps/block, 4 rows/warp, float4 smem loads (FMA-dense).
// INSEL: 0 = xin, 1 = g_aggA, 2 = g_aggB. HSEL: 1/2/3. ASEL: 0/1/2.
// ---------------------------------------------------------------------------
template<int FIN, int FOUT, int INSEL, int HSEL, int ASEL>
__global__ __launch_bounds__(128)
void gat_gemm(const float* __restrict__ xin, const float* __restrict__ W,
              const float* __restrict__ av, const float* __restrict__ dv,
              int rlo, int rhi) {
    constexpr int P = FIN + 4;
    __shared__ float sW[FOUT * P];
    __shared__ __align__(16) float srow[4][4][FIN];
    __shared__ float sA[FOUT];
    __shared__ float sD[FOUT];

    int tid = threadIdx.x;
    for (int i = tid; i < FOUT * FIN; i += 128) {
        int j = i / FIN, k = i % FIN;
        sW[j * P + k] = W[i];
    }
    if (tid < FOUT) { sA[tid] = av[tid]; sD[tid] = dv[tid]; }
    __syncthreads();

    const float* in = (INSEL == 0) ? xin : (INSEL == 1 ? g_aggA : g_aggB);
    float* hdst  = (HSEL == 1) ? g_h1 : (HSEL == 2 ? g_h2 : g_h3);
    float* asOut = (ASEL == 0) ? g_asA : (ASEL == 1 ? g_asB : g_asC);
    float* adOut = (ASEL == 0) ? g_adA : (ASEL == 1 ? g_adB : g_adC);
    int w = tid >> 5, lane = tid & 31;
    int j0 = lane, j1 = 32 + lane;

    for (int row0 = rlo + (blockIdx.x * 4 + w) * 4; row0 < rhi;
         row0 += gridDim.x * 16) {
        int nr = min(4, rhi - row0);
        for (int r = 0; r < nr; r++) {
            const float4* rp = (const float4*)(in + (size_t)(row0 + r) * FIN);
            if (FIN == 128) ((float4*)srow[w][r])[lane] = rp[lane];
            else if (lane < FIN / 4) ((float4*)srow[w][r])[lane] = rp[lane];
        }
        __syncwarp();

        float acc[4][FOUT / 32];
        #pragma unroll
        for (int r = 0; r < 4; r++)
            #pragma unroll
            for (int c = 0; c < FOUT / 32; c++) acc[r][c] = 0.f;

        #pragma unroll
        for (int kq = 0; kq < FIN / 4; kq++) {
            float4 w0 = *(const float4*)&sW[j0 * P + kq * 4];
            float4 w1;
            if (FOUT > 32) w1 = *(const float4*)&sW[j1 * P + kq * 4];
            #pragma unroll
            for (int r = 0; r < 4; r++) {
                float4 rv = ((const float4*)srow[w][r])[kq];
                acc[r][0] = fmaf(rv.x, w0.x, acc[r][0]);
                acc[r][0] = fmaf(rv.y, w0.y, acc[r][0]);
                acc[r][0] = fmaf(rv.z, w0.z, acc[r][0]);
                acc[r][0] = fmaf(rv.w, w0.w, acc[r][0]);
                if (FOUT > 32) {
                    acc[r][1] = fmaf(rv.x, w1.x, acc[r][1]);
                    acc[r][1] = fmaf(rv.y, w1.y, acc[r][1]);
                    acc[r][1] = fmaf(rv.z, w1.z, acc[r][1]);
                    acc[r][1] = fmaf(rv.w, w1.w, acc[r][1]);
                }
            }
        }

        for (int r = 0; r < nr; r++) {
            int row = row0 + r;
            float pa, pd;
            hdst[(size_t)row * FOUT + j0] = acc[r][0];
            pa = acc[r][0] * sA[j0];
            pd = acc[r][0] * sD[j0];
            if (FOUT > 32) {
                hdst[(size_t)row * FOUT + j1] = acc[r][1];
                pa = fmaf(acc[r][1], sA[j1], pa);
                pd = fmaf(acc[r][1], sD[j1], pd);
            }
            #pragma unroll
            for (int o = 16; o > 0; o >>= 1) {
                pa += __shfl_down_sync(0xffffffffu, pa, o);
                pd += __shfl_down_sync(0xffffffffu, pd, o);
            }
            if (lane == 0) { asOut[row] = pa; adOut[row] = pd; }
        }
        __syncwarp();
    }
}

// ---------------------------------------------------------------------------
// CSR gather over node range [lo, hi): warp per dst node, group-per-edge
// float4 layout. MODE 0: h1/asA -> relu(acc/s + b1) -> g_aggA, plus alpha.
// MODE 1: h2/asB -> relu(acc/s + b2) -> g_aggB.
// MODE 2: h3/asC -> acc/s + b3 -> outO.
// ---------------------------------------------------------------------------
template<int FOUT, int MODE>
__global__ __launch_bounds__(256)
void gat_gather(int lo, int hi, const float* __restrict__ bias,
                float* __restrict__ outAlpha, float* __restrict__ outO) {
    constexpr int GSZ = FOUT / 4;      // lanes per group
    constexpr int NG  = 32 / GSZ;      // edges per iteration
    int wg = lo + ((blockIdx.x * blockDim.x + threadIdx.x) >> 5);
    int lane = threadIdx.x & 31;
    if (wg >= hi) return;
    int d = wg;
    int beg = g_off[d], end = g_off[d + 1];
    const float* hsrc = (MODE == 0) ? g_h1 : (MODE == 1 ? g_h2 : g_h3);
    const float* asv  = (MODE == 0) ? g_asA : (MODE == 1 ? g_asB : g_asC);
    float ad = (MODE == 0) ? g_adA[d] : (MODE == 1 ? g_adB[d] : g_adC[d]);
    int g = lane / GSZ, fl = lane % GSZ;

    float4 acc = make_float4(0.f, 0.f, 0.f, 0.f);
    float s = 0.f;

    for (int p0 = beg; p0 < end; p0 += 32) {
        int cnt = min(32, end - p0);
        int src_l = 0;
        float w_l = 0.f;
        if (lane < cnt) {
            src_l = g_csr_src[p0 + lane];
            float v = asv[src_l] + ad;
            v = v > 0.f ? v : NEG_SLOPE * v;
            w_l = __expf(v);
            if (MODE == 0) g_ew[p0 + lane] = w_l;
        }
        #pragma unroll 2
        for (int q = 0; q < cnt; q += NG) {
            int idx = q + g;
            float wh  = __shfl_sync(0xffffffffu, w_l, idx & 31);
            int  srch = __shfl_sync(0xffffffffu, src_l, idx & 31);
            float w2 = (idx < cnt) ? wh : 0.f;
            float4 hv = *(const float4*)&hsrc[(size_t)srch * FOUT + fl * 4];
            acc.x = fmaf(w2, hv.x, acc.x);
            acc.y = fmaf(w2, hv.y, acc.y);
            acc.z = fmaf(w2, hv.z, acc.z);
            acc.w = fmaf(w2, hv.w, acc.w);
            s += w2;
        }
    }
    // combine groups
    #pragma unroll
    for (int off = GSZ; off < 32; off <<= 1) {
        s     += __shfl_xor_sync(0xffffffffu, s, off);
        acc.x += __shfl_xor_sync(0xffffffffu, acc.x, off);
        acc.y += __shfl_xor_sync(0xffffffffu, acc.y, off);
        acc.z += __shfl_xor_sync(0xffffffffu, acc.z, off);
        acc.w += __shfl_xor_sync(0xffffffffu, acc.w, off);
    }
    float sinv = 1.f / (s + EPS_F);

    if (lane < GSZ) {
        float4 b = *(const float4*)&bias[fl * 4];
        float4 o;
        if (MODE == 2) {
            o.x = fmaf(acc.x, sinv, b.x);
            o.y = fmaf(acc.y, sinv, b.y);
            o.z = fmaf(acc.z, sinv, b.z);
            o.w = fmaf(acc.w, sinv, b.w);
            *(float4*)&outO[(size_t)d * FOUT + fl * 4] = o;
        } else {
            o.x = fmaxf(fmaf(acc.x, sinv, b.x), 0.f);
            o.y = fmaxf(fmaf(acc.y, sinv, b.y), 0.f);
            o.z = fmaxf(fmaf(acc.z, sinv, b.z), 0.f);
            o.w = fmaxf(fmaf(acc.w, sinv, b.w), 0.f);
            float* outp = (MODE == 0) ? g_aggA : g_aggB;
            *(float4*)&outp[(size_t)d * FOUT + fl * 4] = o;
        }
    }

    if (MODE == 0) {
        for (int p = beg + lane; p < end; p += 32)
            outAlpha[g_csr_eid[p]] = g_ew[p] * sinv;
    }
}

// ---------------------------------------------------------------------------

extern "C" void kernel_launch(void* const* d_in, const int* in_sizes, int n_in,
                              void* d_out, int out_size) {
    const float* x    = (const float*)d_in[0];
    const int*   ei32 = (const int*)d_in[1];
    const float* W1 = (const float*)d_in[2];
    const float* a1s = (const float*)d_in[3];
    const float* a1d = (const float*)d_in[4];
    const float* b1 = (const float*)d_in[5];
    const float* W2 = (const float*)d_in[6];
    const float* a2s = (const float*)d_in[7];
    const float* a2d = (const float*)d_in[8];
    const float* b2 = (const float*)d_in[9];
    const float* W3 = (const float*)d_in[10];
    const float* a3s = (const float*)d_in[11];
    const float* a3d = (const float*)d_in[12];
    const float* b3 = (const float*)d_in[13];

    const int N  = in_sizes[0] / 128;     // 50000
    const int E  = in_sizes[1] / 2;       // 800000
    const int Ep = E + N;                 // with self loops
    const int Nh = N / 2;

    float* out      = (float*)d_out;
    float* outAlpha = out + 2 * (size_t)Ep;
    float* outO     = out + 3 * (size_t)Ep;

    const int TB = 256;
    int ebl = (Ep + TB - 1) / TB;
    int nb = (N + 1023) / 1024;
    int gemm_full = (N + 15) / 16;
    int gemm_half = (Nh + 15) / 16;
    int gemm_rest = (N - Nh + 15) / 16;
    int gath_half = (Nh + 7) / 8;
    int gath_rest = (N - Nh + 7) / 8;
    int gath_full = (N + 7) / 8;

    static cudaStream_t s2 = nullptr;
    static cudaEvent_t evFork = nullptr, evJoin = nullptr,
                       evA = nullptr, evM2A = nullptr,
                       evC = nullptr, evM3A = nullptr;
    if (!s2) {
        cudaStreamCreateWithFlags(&s2, cudaStreamNonBlocking);
        cudaEventCreateWithFlags(&evFork, cudaEventDisableTiming);
        cudaEventCreateWithFlags(&evJoin, cudaEventDisableTiming);
        cudaEventCreateWithFlags(&evA, cudaEventDisableTiming);
        cudaEventCreateWithFlags(&evM2A, cudaEventDisableTiming);
        cudaEventCreateWithFlags(&evC, cudaEventDisableTiming);
        cudaEventCreateWithFlags(&evM3A, cudaEventDisableTiming);
    }

    // fork: GEMM1 on s2, independent of edge preprocessing
    cudaEventRecord(evFork, 0);
    cudaStreamWaitEvent(s2, evFork, 0);
    gat_gemm<128, 64, 0, 1, 0><<<gemm_full, 128, 0, s2>>>(x, W1, a1s, a1d, 0, N);
    cudaEventRecord(evJoin, s2);

    // preprocessing chain on main stream
    init_kernel<<<1, 32>>>(ei32);
    build_edges<<<ebl, TB>>>(ei32, E, Ep, N, out);
    scan_single<<<nb, 1024>>>(N, nb);
    place_edges<<<ebl, TB>>>(ei32, E, Ep, N);

    cudaStreamWaitEvent(0, evJoin, 0);

    // ---- layer 1 gather (half a), then pipeline gemm2_a vs gather1_b ----
    gat_gather<64, 0><<<gath_half, TB>>>(0, Nh, b1, outAlpha, nullptr);
    cudaEventRecord(evA, 0);
    cudaStreamWaitEvent(s2, evA, 0);
    gat_gemm<64, 64, 1, 2, 1><<<gemm_half, 128, 0, s2>>>(nullptr, W2, a2s, a2d, 0, Nh);
    cudaEventRecord(evM2A, s2);

    gat_gather<64, 0><<<gath_rest, TB>>>(Nh, N, b1, outAlpha, nullptr);
    gat_gemm<64, 64, 1, 2, 1><<<gemm_rest, 128>>>(nullptr, W2, a2s, a2d, Nh, N);
    cudaStreamWaitEvent(0, evM2A, 0);

    // ---- layer 2 gather (half a), then pipeline gemm3_a vs gather2_b ----
    gat_gather<64, 1><<<gath_half, TB>>>(0, Nh, b2, nullptr, nullptr);
    cudaEventRecord(evC, 0);
    cudaStreamWaitEvent(s2, evC, 0);
    gat_gemm<64, 32, 2, 3, 2><<<gemm_half, 128, 0, s2>>>(nullptr, W3, a3s, a3d, 0, Nh);
    cudaEventRecord(evM3A, s2);

    gat_gather<64, 1><<<gath_rest, TB>>>(Nh, N, b2, nullptr, nullptr);
    gat_gemm<64, 32, 2, 3, 2><<<gemm_rest, 128>>>(nullptr, W3, a3s, a3d, Nh, N);
    cudaStreamWaitEvent(0, evM3A, 0);

    // ---- layer 3 gather (full) ----
    gat_gather<32, 2><<<gath_full, TB>>>(0, N, b3, nullptr, outO);
}

// round 11
// speedup vs baseline: 1.0575x; 1.0575x over previous
#include <cuda_runtime.h>

#define EPS_F 1e-16f
#define NEG_SLOPE 0.2f

static const int MAXN = 50048;
static const int MAXE = 850048;
static const int NBMAX = 64;

// scratch (device globals — no allocation allowed)
__device__ int   g_deg[MAXN];          // zeroed at load; re-zeroed by scan_phase3
__device__ int   g_off[MAXN + 1];
__device__ int   g_cur[MAXN];
__device__ int   g_csr_src[MAXE];
__device__ int   g_csr_eid[MAXE];
__device__ float g_ew[MAXE];
__device__ int   g_bsum[NBMAX];
__device__ __align__(16) float g_h[(size_t)MAXN * 64];
__device__ __align__(16) float g_aggA[(size_t)MAXN * 64];
__device__ __align__(16) float g_aggB[(size_t)MAXN * 64];
__device__ float g_as[MAXN];
__device__ float g_ad[MAXN];
__device__ int   g_is64;               // unused placeholder (detection is per-block now)

// ---------------------------------------------------------------------------
// Per-block edge-dtype detection: thread 0 inspects the first 64 odd 32-bit
// words (all-zero <=> little-endian int64 with values < 2^31). L2-hot.
// ---------------------------------------------------------------------------
__device__ __forceinline__ int detect_is64_block(const int* __restrict__ ei32,
                                                 int* s_flag) {
    if (threadIdx.x == 0) {
        int all_zero = 1;
        #pragma unroll
        for (int k = 0; k < 64; k++)
            if (ei32[2 * k + 1] != 0) { all_zero = 0; break; }
        *s_flag = all_zero;
    }
    __syncthreads();
    return *s_flag;
}

__device__ __forceinline__ void load_edge(const int* __restrict__ ei32, int is64,
                                          int e, int E, int n, int& s, int& d) {
    if (e < E) {
        if (is64) {
            const long long* ei = (const long long*)ei32;
            s = (int)ei[e]; d = (int)ei[E + e];
        } else {
            s = ei32[e]; d = ei32[E + e];
        }
    } else {
        s = d = e - E;   // self loop
    }
    s = min(max(s, 0), n - 1);
    d = min(max(d, 0), n - 1);
}

// Count per-dst degree; emit stacked (src,dst) as float at head of d_out.
__global__ void build_edges(const int* __restrict__ ei32, int E, int Ep, int n,
                            float* __restrict__ outIdx) {
    __shared__ int s_is64;
    int is64 = detect_is64_block(ei32, &s_is64);
    int e = blockIdx.x * blockDim.x + threadIdx.x;
    if (e >= Ep) return;
    int s, d;
    load_edge(ei32, is64, e, E, n, s, d);
    atomicAdd(&g_deg[d], 1);
    outIdx[e]      = (float)s;
    outIdx[Ep + e] = (float)d;
}

// ---------------------------------------------------------------------------
// Two-phase scan: phase1 = per-1024-chunk sums; phase3 = per-chunk scan with
// self-computed base (<=49 bsums, L2-hot) + consume-and-reset of g_deg.
// ---------------------------------------------------------------------------
__global__ void scan_phase1(int n) {
    __shared__ int warpsum[32];
    int tid = threadIdx.x, lane = tid & 31, wid = tid >> 5;
    int i = blockIdx.x * 1024 + tid;
    int v = (i < n) ? g_deg[i] : 0;
    #pragma unroll
    for (int off = 16; off > 0; off >>= 1)
        v += __shfl_down_sync(0xffffffffu, v, off);
    if (lane == 0) warpsum[wid] = v;
    __syncthreads();
    if (wid == 0) {
        int t = warpsum[lane];
        #pragma unroll
        for (int off = 16; off > 0; off >>= 1)
            t += __shfl_down_sync(0xffffffffu, t, off);
        if (lane == 0) g_bsum[blockIdx.x] = t;
    }
}

__global__ void scan_phase3(int n) {
    __shared__ int warpsum[32];
    __shared__ int s_base;
    int tid = threadIdx.x, lane = tid & 31, wid = tid >> 5;
    if (tid == 0) {
        int b = 0;
        for (int i = 0; i < blockIdx.x; i++) b += g_bsum[i];
        s_base = b;
    }
    int i = blockIdx.x * 1024 + tid;
    int v = (i < n) ? g_deg[i] : 0;
    if (i < n) g_deg[i] = 0;                 // reset for next replay
    int incl = v;
    #pragma unroll
    for (int off = 1; off < 32; off <<= 1) {
        int t = __shfl_up_sync(0xffffffffu, incl, off);
        if (lane >= off) incl += t;
    }
    if (lane == 31) warpsum[wid] = incl;
    __syncthreads();
    if (wid == 0) {
        int ws = warpsum[lane];
        int wincl = ws;
        #pragma unroll
        for (int off = 1; off < 32; off <<= 1) {
            int t = __shfl_up_sync(0xffffffffu, wincl, off);
            if (lane >= off) wincl += t;
        }
        warpsum[lane] = wincl - ws;
    }
    __syncthreads();
    int excl = incl - v + warpsum[wid] + s_base;
    if (i < n) {
        g_off[i] = excl;
        g_cur[i] = excl;
        if (i == n - 1) g_off[n] = excl + v;
    }
}

__global__ void place_edges(const int* __restrict__ ei32, int E, int Ep, int n) {
    __shared__ int s_is64;
    int is64 = detect_is64_block(ei32, &s_is64);
    int e = blockIdx.x * blockDim.x + threadIdx.x;
    if (e >= Ep) return;
    int s, d;
    load_edge(ei32, is64, e, E, n, s, d);
    int pos = atomicAdd(&g_cur[d], 1);
    g_csr_src[pos] = s;
    g_csr_eid[pos] = e;
}

// ---------------------------------------------------------------------------
// GEMM: h = in @ W^T ; g_as = h.a_src ; g_ad = h.a_dst.
// 4 warps/block, 4 rows/warp, float4 smem loads (FMA-dense).
// INSEL: 0 = xin param, 1 = g_aggA, 2 = g_aggB.
// ---------------------------------------------------------------------------
template<int FIN, int FOUT, int INSEL>
__global__ __launch_bounds__(128)
void gat_gemm(const float* __restrict__ xin, const float* __restrict__ W,
              const float* __restrict__ av, const float* __restrict__ dv,
              int n) {
    constexpr int P = FIN + 4;
    __shared__ float sW[FOUT * P];
    __shared__ __align__(16) float srow[4][4][FIN];
    __shared__ float sA[FOUT];
    __shared__ float sD[FOUT];

    int tid = threadIdx.x;
    for (int i = tid; i < FOUT * FIN; i += 128) {
        int j = i / FIN, k = i % FIN;
        sW[j * P + k] = W[i];
    }
    if (tid < FOUT) { sA[tid] = av[tid]; sD[tid] = dv[tid]; }
    __syncthreads();

    const float* in = (INSEL == 0) ? xin : (INSEL == 1 ? g_aggA : g_aggB);
    int w = tid >> 5, lane = tid & 31;
    int j0 = lane, j1 = 32 + lane;

    for (int row0 = (blockIdx.x * 4 + w) * 4; row0 < n; row0 += gridDim.x * 16) {
        int nr = min(4, n - row0);
        for (int r = 0; r < nr; r++) {
            const float4* rp = (const float4*)(in + (size_t)(row0 + r) * FIN);
            if (FIN == 128) ((float4*)srow[w][r])[lane] = rp[lane];
            else if (lane < FIN / 4) ((float4*)srow[w][r])[lane] = rp[lane];
        }
        __syncwarp();

        float acc[4][FOUT / 32];
        #pragma unroll
        for (int r = 0; r < 4; r++)
            #pragma unroll
            for (int c = 0; c < FOUT / 32; c++) acc[r][c] = 0.f;

        #pragma unroll
        for (int kq = 0; kq < FIN / 4; kq++) {
            float4 w0 = *(const float4*)&sW[j0 * P + kq * 4];
            float4 w1;
            if (FOUT > 32) w1 = *(const float4*)&sW[j1 * P + kq * 4];
            #pragma unroll
            for (int r = 0; r < 4; r++) {
                float4 rv = ((const float4*)srow[w][r])[kq];
                acc[r][0] = fmaf(rv.x, w0.x, acc[r][0]);
                acc[r][0] = fmaf(rv.y, w0.y, acc[r][0]);
                acc[r][0] = fmaf(rv.z, w0.z, acc[r][0]);
                acc[r][0] = fmaf(rv.w, w0.w, acc[r][0]);
                if (FOUT > 32) {
                    acc[r][1] = fmaf(rv.x, w1.x, acc[r][1]);
                    acc[r][1] = fmaf(rv.y, w1.y, acc[r][1]);
                    acc[r][1] = fmaf(rv.z, w1.z, acc[r][1]);
                    acc[r][1] = fmaf(rv.w, w1.w, acc[r][1]);
                }
            }
        }

        for (int r = 0; r < nr; r++) {
            int row = row0 + r;
            float pa, pd;
            g_h[(size_t)row * FOUT + j0] = acc[r][0];
            pa = acc[r][0] * sA[j0];
            pd = acc[r][0] * sD[j0];
            if (FOUT > 32) {
                g_h[(size_t)row * FOUT + j1] = acc[r][1];
                pa = fmaf(acc[r][1], sA[j1], pa);
                pd = fmaf(acc[r][1], sD[j1], pd);
            }
            #pragma unroll
            for (int o = 16; o > 0; o >>= 1) {
                pa += __shfl_down_sync(0xffffffffu, pa, o);
                pd += __shfl_down_sync(0xffffffffu, pd, o);
            }
            if (lane == 0) { g_as[row] = pa; g_ad[row] = pd; }
        }
        __syncwarp();
    }
}

// ---------------------------------------------------------------------------
// CSR gather: warp per dst node, group-per-edge float4 layout.
// MODE 0 (layer1): out = relu(acc/s + b1) -> g_aggA, plus coalesced alpha.
// MODE 1 (layer2): out = relu(acc/s + b2) -> g_aggB.
// MODE 2 (layer3): out = acc/s + b3 -> outO.
// ---------------------------------------------------------------------------
template<int FOUT, int MODE>
__global__ __launch_bounds__(256)
void gat_gather(int n, const float* __restrict__ bias,
                float* __restrict__ outAlpha, float* __restrict__ outO) {
    constexpr int GSZ = FOUT / 4;      // lanes per group
    constexpr int NG  = 32 / GSZ;      // edges per iteration
    int wg = (blockIdx.x * blockDim.x + threadIdx.x) >> 5;
    int lane = threadIdx.x & 31;
    if (wg >= n) return;
    int d = wg;
    int beg = g_off[d], end = g_off[d + 1];
    float ad = g_ad[d];
    int g = lane / GSZ, fl = lane % GSZ;

    float4 acc = make_float4(0.f, 0.f, 0.f, 0.f);
    float s = 0.f;

    for (int p0 = beg; p0 < end; p0 += 32) {
        int cnt = min(32, end - p0);
        int src_l = 0;
        float w_l = 0.f;
        if (lane < cnt) {
            src_l = g_csr_src[p0 + lane];
            float v = g_as[src_l] + ad;
            v = v > 0.f ? v : NEG_SLOPE * v;
            w_l = __expf(v);
            if (MODE == 0) g_ew[p0 + lane] = w_l;
        }
        #pragma unroll 2
        for (int q = 0; q < cnt; q += NG) {
            int idx = q + g;
            float wh  = __shfl_sync(0xffffffffu, w_l, idx & 31);
            int  srch = __shfl_sync(0xffffffffu, src_l, idx & 31);
            float w2 = (idx < cnt) ? wh : 0.f;
            float4 hv = *(const float4*)&g_h[(size_t)srch * FOUT + fl * 4];
            acc.x = fmaf(w2, hv.x, acc.x);
            acc.y = fmaf(w2, hv.y, acc.y);
            acc.z = fmaf(w2, hv.z, acc.z);
            acc.w = fmaf(w2, hv.w, acc.w);
            s += w2;
        }
    }
    // combine groups
    #pragma unroll
    for (int off = GSZ; off < 32; off <<= 1) {
        s     += __shfl_xor_sync(0xffffffffu, s, off);
        acc.x += __shfl_xor_sync(0xffffffffu, acc.x, off);
        acc.y += __shfl_xor_sync(0xffffffffu, acc.y, off);
        acc.z += __shfl_xor_sync(0xffffffffu, acc.z, off);
        acc.w += __shfl_xor_sync(0xffffffffu, acc.w, off);
    }
    float sinv = 1.f / (s + EPS_F);

    if (lane < GSZ) {
        float4 b = *(const float4*)&bias[fl * 4];
        float4 o;
        if (MODE == 2) {
            o.x = fmaf(acc.x, sinv, b.x);
            o.y = fmaf(acc.y, sinv, b.y);
            o.z = fmaf(acc.z, sinv, b.z);
            o.w = fmaf(acc.w, sinv, b.w);
            *(float4*)&outO[(size_t)d * FOUT + fl * 4] = o;
        } else {
            o.x = fmaxf(fmaf(acc.x, sinv, b.x), 0.f);
            o.y = fmaxf(fmaf(acc.y, sinv, b.y), 0.f);
            o.z = fmaxf(fmaf(acc.z, sinv, b.z), 0.f);
            o.w = fmaxf(fmaf(acc.w, sinv, b.w), 0.f);
            float* outp = (MODE == 0) ? g_aggA : g_aggB;
            *(float4*)&outp[(size_t)d * FOUT + fl * 4] = o;
        }
    }

    if (MODE == 0) {
        for (int p = beg + lane; p < end; p += 32)
            outAlpha[g_csr_eid[p]] = g_ew[p] * sinv;
    }
}

// ---------------------------------------------------------------------------

extern "C" void kernel_launch(void* const* d_in, const int* in_sizes, int n_in,
                              void* d_out, int out_size) {
    const float* x    = (const float*)d_in[0];
    const int*   ei32 = (const int*)d_in[1];
    const float* W1 = (const float*)d_in[2];
    const float* a1s = (const float*)d_in[3];
    const float* a1d = (const float*)d_in[4];
    const float* b1 = (const float*)d_in[5];
    const float* W2 = (const float*)d_in[6];
    const float* a2s = (const float*)d_in[7];
    const float* a2d = (const float*)d_in[8];
    const float* b2 = (const float*)d_in[9];
    const float* W3 = (const float*)d_in[10];
    const float* a3s = (const float*)d_in[11];
    const float* a3d = (const float*)d_in[12];
    const float* b3 = (const float*)d_in[13];

    const int N  = in_sizes[0] / 128;     // 50000
    const int E  = in_sizes[1] / 2;       // 800000
    const int Ep = E + N;                 // with self loops

    float* out      = (float*)d_out;
    float* outAlpha = out + 2 * (size_t)Ep;
    float* outO     = out + 3 * (size_t)Ep;

    const int TB = 256;
    int ebl = (Ep + TB - 1) / TB;
    int nb = (N + 1023) / 1024;
    int gemm_grid = (N + 15) / 16;
    int gath_grid = (N + 7) / 8;

    // one-time side-stream for overlapping GEMM1 with preprocessing
    static cudaStream_t s2 = nullptr;
    static cudaEvent_t evFork = nullptr, evJoin = nullptr;
    if (!s2) {
        cudaStreamCreateWithFlags(&s2, cudaStreamNonBlocking);
        cudaEventCreateWithFlags(&evFork, cudaEventDisableTiming);
        cudaEventCreateWithFlags(&evJoin, cudaEventDisableTiming);
    }

    // fork: GEMM1 runs on s2, independent of edge preprocessing
    cudaEventRecord(evFork, 0);
    cudaStreamWaitEvent(s2, evFork, 0);
    gat_gemm<128, 64, 0><<<gemm_grid, 128, 0, s2>>>(x, W1, a1s, a1d, N);
    cudaEventRecord(evJoin, s2);

    // preprocessing chain on main stream (no init kernel: dtype detection is
    // per-block; g_deg zeroing is consume-and-reset inside scan_phase3)
    build_edges<<<ebl, TB>>>(ei32, E, Ep, N, out);
    scan_phase1<<<nb, 1024>>>(N);
    scan_phase3<<<nb, 1024>>>(N);
    place_edges<<<ebl, TB>>>(ei32, E, Ep, N);

    // join: gather1 needs both CSR and GEMM1 results
    cudaStreamWaitEvent(0, evJoin, 0);

    // ---- layer 1: 128 -> 64 ----
    gat_gather<64, 0><<<gath_grid, TB>>>(N, b1, outAlpha, nullptr);

    // ---- layer 2: 64 -> 64 ----
    gat_gemm<64, 64, 1><<<gemm_grid, 128>>>(nullptr, W2, a2s, a2d, N);
    gat_gather<64, 1><<<gath_grid, TB>>>(N, b2, nullptr, nullptr);

    // ---- layer 3: 64 -> 32 ----
    gat_gemm<64, 32, 2><<<gemm_grid, 128>>>(nullptr, W3, a3s, a3d, N);
    gat_gather<32, 2><<<gath_grid, TB>>>(N, b3, nullptr, outO);
}